// round 1
// baseline (speedup 1.0000x reference)
#include <cuda_runtime.h>
#include <cuda_bf16.h>
#include <math.h>

#define NN 100000
#define EE 250000
#define GG 4000
#define DD 300
#define D2 600
#define LL 5
#define EPS 1e-5f

// ---------------- scratch (device globals; no allocation) ----------------
__device__ float g_h[(size_t)NN * DD];     // node state h
__device__ float g_aggr[(size_t)NN * DD];  // GIN aggregate
__device__ float g_hid[(size_t)NN * D2];   // MLP hidden
__device__ float g_pool[(size_t)GG * DD];  // pooled per-graph
__device__ float g_vn[(size_t)GG * DD];    // virtual node state
__device__ float g_cnt[GG];                // node counts per graph

// ---------------- small utility kernels ----------------
__global__ void k_zero(float* p, long n) {
    long i = (long)blockIdx.x * blockDim.x + threadIdx.x;
    if (i < n) p[i] = 0.f;
}

__global__ void k_count(const int* __restrict__ batch, float* cnt, int n) {
    int i = blockIdx.x * blockDim.x + threadIdx.x;
    if (i < n) atomicAdd(&cnt[batch[i]], 1.f);
}

__global__ void k_init_h(const int* __restrict__ x_atom, const int* __restrict__ x_chir,
                         const float* __restrict__ emb1, const float* __restrict__ emb2,
                         const float* __restrict__ vn_emb, float* __restrict__ h, long total) {
    long idx = (long)blockIdx.x * blockDim.x + threadIdx.x;
    if (idx >= total) return;
    int i = (int)(idx / DD);
    int d = (int)(idx % DD);
    h[idx] = emb1[(size_t)x_atom[i] * DD + d] + emb2[(size_t)x_chir[i] * DD + d] + vn_emb[d];
}

__global__ void k_init_vn(const float* __restrict__ vn_emb, float* __restrict__ vn, long total) {
    long idx = (long)blockIdx.x * blockDim.x + threadIdx.x;
    if (idx >= total) return;
    vn[idx] = vn_emb[idx % DD];
}

// aggr = h + selfloop_emb
__global__ void k_aggr_init(const float* __restrict__ h,
                            const float* __restrict__ e1self, const float* __restrict__ e2self,
                            float* __restrict__ aggr, long total) {
    long idx = (long)blockIdx.x * blockDim.x + threadIdx.x;
    if (idx >= total) return;
    int d = (int)(idx % DD);
    aggr[idx] = h[idx] + e1self[d] + e2self[d];
}

// one warp per edge: aggr[dst] += h[src] + e1[type] + e2[dir]
__global__ void k_scatter(const float* __restrict__ h,
                          const int* __restrict__ src, const int* __restrict__ dst,
                          const int* __restrict__ et, const int* __restrict__ ed,
                          const float* __restrict__ e1, const float* __restrict__ e2,
                          float* __restrict__ aggr, int E) {
    int warp = blockIdx.x * (blockDim.x >> 5) + (threadIdx.x >> 5);
    if (warp >= E) return;
    int lane = threadIdx.x & 31;
    int s = src[warp], t = dst[warp];
    const float* ea = e1 + (size_t)et[warp] * DD;
    const float* eb = e2 + (size_t)ed[warp] * DD;
    const float* hs = h + (size_t)s * DD;
    float* at = aggr + (size_t)t * DD;
    for (int d = lane; d < DD; d += 32)
        atomicAdd(&at[d], hs[d] + ea[d] + eb[d]);
}

// one warp per node: pool[batch[i]] += z[i]
__global__ void k_pool(const float* __restrict__ z, const int* __restrict__ batch,
                       float* __restrict__ pool, int n) {
    int warp = blockIdx.x * (blockDim.x >> 5) + (threadIdx.x >> 5);
    if (warp >= n) return;
    int lane = threadIdx.x & 31;
    int b = batch[warp];
    const float* zs = z + (size_t)warp * DD;
    float* pd = pool + (size_t)b * DD;
    for (int d = lane; d < DD; d += 32)
        atomicAdd(&pd[d], zs[d]);
}

// h[i] += vn[batch[i]]
__global__ void k_addvn(float* __restrict__ h, const float* __restrict__ vn,
                        const int* __restrict__ batch, long total) {
    long idx = (long)blockIdx.x * blockDim.x + threadIdx.x;
    if (idx >= total) return;
    int i = (int)(idx / DD);
    int d = (int)(idx % DD);
    h[idx] += vn[(size_t)batch[i] * DD + d];
}

// virtual node MLP: one block (512 threads) per graph
__global__ void k_vn(float* __restrict__ vn, const float* __restrict__ pooled,
                     const float* __restrict__ cnt,
                     const float* __restrict__ w1, const float* __restrict__ b1,
                     const float* __restrict__ lng, const float* __restrict__ lnb,
                     const float* __restrict__ w2, const float* __restrict__ b2) {
    int g = blockIdx.x;
    int tid = threadIdx.x;
    __shared__ float s_in[DD];
    __shared__ float s_t[DD];
    __shared__ float s_red[512];

    float c = fmaxf(cnt[g], 1.f);
    if (tid < DD) s_in[tid] = pooled[(size_t)g * DD + tid] / c + vn[(size_t)g * DD + tid];
    __syncthreads();

    float t = 0.f;
    if (tid < DD) {
        float acc = b1[tid];
        #pragma unroll 4
        for (int k = 0; k < DD; k++) acc = fmaf(s_in[k], w1[(size_t)k * DD + tid], acc);
        t = acc;
    }
    // mean
    s_red[tid] = (tid < DD) ? t : 0.f;
    __syncthreads();
    for (int s = 256; s > 0; s >>= 1) {
        if (tid < s) s_red[tid] += s_red[tid + s];
        __syncthreads();
    }
    float mu = s_red[0] / DD;
    __syncthreads();
    // var (population)
    float dmu = (tid < DD) ? (t - mu) : 0.f;
    s_red[tid] = dmu * dmu;
    __syncthreads();
    for (int s = 256; s > 0; s >>= 1) {
        if (tid < s) s_red[tid] += s_red[tid + s];
        __syncthreads();
    }
    float var = s_red[0] / DD;
    __syncthreads();

    if (tid < DD) {
        float x = (t - mu) * rsqrtf(var + EPS) * lng[tid] + lnb[tid];
        s_t[tid] = fmaxf(x, 0.f);
    }
    __syncthreads();

    if (tid < DD) {
        float acc = b2[tid];
        #pragma unroll 4
        for (int k = 0; k < DD; k++) acc = fmaf(s_t[k], w2[(size_t)k * DD + tid], acc);
        vn[(size_t)g * DD + tid] = acc;
    }
}

// ---------------- SGEMM with fused epilogue ----------------
// C[n,m] = epilogue( A[n,k] @ B[k,m] + bias[m] )
// mode 0: ReLU(x+bias)          (MLP hidden)
// mode 1: BN(x+bias) then ReLU  (layer output, not last)
// mode 2: BN(x+bias)            (last layer)
#define BM 64
#define BN 64
#define BK 16
__global__ __launch_bounds__(256) void k_gemm(const float* __restrict__ A,
                                              const float* __restrict__ B,
                                              float* __restrict__ C,
                                              int Nrows, int K, int M,
                                              const float* __restrict__ bias,
                                              const float* __restrict__ bng,
                                              const float* __restrict__ bnb,
                                              const float* __restrict__ bnm,
                                              const float* __restrict__ bnv,
                                              int mode) {
    __shared__ float As[BK][BM + 1];
    __shared__ float Bs[BK][BN];
    int tid = threadIdx.x;           // 256
    int tx = tid & 15, ty = tid >> 4;
    int row0 = blockIdx.y * BM;
    int col0 = blockIdx.x * BN;
    float acc[4][4] = {};

    for (int k0 = 0; k0 < K; k0 += BK) {
        #pragma unroll
        for (int i = 0; i < 4; i++) {
            int idx = tid + i * 256;
            int m = idx / BK;
            int k = idx % BK;
            int gr = row0 + m, gk = k0 + k;
            As[k][m] = (gr < Nrows && gk < K) ? A[(size_t)gr * K + gk] : 0.f;
        }
        #pragma unroll
        for (int i = 0; i < 4; i++) {
            int idx = tid + i * 256;
            int k = idx / BN;
            int n = idx % BN;
            int gk = k0 + k, gc = col0 + n;
            Bs[k][n] = (gk < K && gc < M) ? B[(size_t)gk * M + gc] : 0.f;
        }
        __syncthreads();
        #pragma unroll
        for (int k = 0; k < BK; k++) {
            float a[4], b[4];
            #pragma unroll
            for (int r = 0; r < 4; r++) a[r] = As[k][ty * 4 + r];
            #pragma unroll
            for (int c = 0; c < 4; c++) b[c] = Bs[k][tx * 4 + c];
            #pragma unroll
            for (int r = 0; r < 4; r++)
                #pragma unroll
                for (int c = 0; c < 4; c++)
                    acc[r][c] = fmaf(a[r], b[c], acc[r][c]);
        }
        __syncthreads();
    }

    #pragma unroll
    for (int r = 0; r < 4; r++) {
        int gr = row0 + ty * 4 + r;
        if (gr >= Nrows) continue;
        #pragma unroll
        for (int c = 0; c < 4; c++) {
            int gc = col0 + tx * 4 + c;
            if (gc >= M) continue;
            float v = acc[r][c] + bias[gc];
            if (mode == 0) {
                v = fmaxf(v, 0.f);
            } else {
                float sc = bng[gc] * rsqrtf(bnv[gc] + EPS);
                v = (v - bnm[gc]) * sc + bnb[gc];
                if (mode == 1) v = fmaxf(v, 0.f);
            }
            C[(size_t)gr * M + gc] = v;
        }
    }
}

// ---------------- launch ----------------
extern "C" void kernel_launch(void* const* d_in, const int* in_sizes, int n_in,
                              void* d_out, int out_size) {
    const int*   x_atom  = (const int*)d_in[0];
    const int*   x_chir  = (const int*)d_in[1];
    const int*   src     = (const int*)d_in[2];
    const int*   dst     = (const int*)d_in[3];
    const int*   etype   = (const int*)d_in[4];
    const int*   edir    = (const int*)d_in[5];
    const int*   batch   = (const int*)d_in[6];
    const float* x_emb1  = (const float*)d_in[7];
    const float* x_emb2  = (const float*)d_in[8];
    const float* edge_e1 = (const float*)d_in[9];    // [L,6,D]
    const float* edge_e2 = (const float*)d_in[10];   // [L,3,D]
    const float* mlp_w1  = (const float*)d_in[11];   // [L,D,2D]
    const float* mlp_b1  = (const float*)d_in[12];   // [L,2D]
    const float* mlp_w2  = (const float*)d_in[13];   // [L,2D,D]
    const float* mlp_b2  = (const float*)d_in[14];   // [L,D]
    const float* bng     = (const float*)d_in[15];
    const float* bnb     = (const float*)d_in[16];
    const float* bnm     = (const float*)d_in[17];
    const float* bnv     = (const float*)d_in[18];
    const float* vn_emb  = (const float*)d_in[19];
    const float* vn_w1   = (const float*)d_in[20];   // [L-1,D,D]
    const float* vn_b1   = (const float*)d_in[21];
    const float* vn_lng  = (const float*)d_in[22];
    const float* vn_lnb  = (const float*)d_in[23];
    const float* vn_w2   = (const float*)d_in[24];
    const float* vn_b2   = (const float*)d_in[25];
    float* out = (float*)d_out;

    float *p_h, *p_aggr, *p_hid, *p_pool, *p_vn, *p_cnt;
    cudaGetSymbolAddress((void**)&p_h, g_h);
    cudaGetSymbolAddress((void**)&p_aggr, g_aggr);
    cudaGetSymbolAddress((void**)&p_hid, g_hid);
    cudaGetSymbolAddress((void**)&p_pool, g_pool);
    cudaGetSymbolAddress((void**)&p_vn, g_vn);
    cudaGetSymbolAddress((void**)&p_cnt, g_cnt);

    const long ND = (long)NN * DD;
    const long GD = (long)GG * DD;
    const int TPB = 256;
    dim3 bElem((unsigned)((ND + TPB - 1) / TPB));
    dim3 bGD((unsigned)((GD + TPB - 1) / TPB));

    // counts
    k_zero<<<(GG + TPB - 1) / TPB, TPB>>>(p_cnt, GG);
    k_count<<<(NN + TPB - 1) / TPB, TPB>>>(batch, p_cnt, NN);

    // h0 and vn0
    k_init_h<<<bElem, TPB>>>(x_atom, x_chir, x_emb1, x_emb2, vn_emb, p_h, ND);
    k_init_vn<<<bGD, TPB>>>(vn_emb, p_vn, GD);

    for (int l = 0; l < LL; l++) {
        const float* e1l = edge_e1 + (size_t)l * 6 * DD;
        const float* e2l = edge_e2 + (size_t)l * 3 * DD;
        const float* e1self = e1l + 4 * DD;
        const float* e2self = e2l;  // dir 0

        // aggr = h + selfloop
        k_aggr_init<<<bElem, TPB>>>(p_h, e1self, e2self, p_aggr, ND);
        // scatter messages
        k_scatter<<<(EE + 3) / 4, 128>>>(p_h, src, dst, etype, edir, e1l, e2l, p_aggr, EE);

        // hidden = ReLU(aggr @ W1 + b1)   [N, 600]
        {
            dim3 grid((D2 + BN - 1) / BN, (NN + BM - 1) / BM);
            k_gemm<<<grid, 256>>>(p_aggr, mlp_w1 + (size_t)l * DD * D2, p_hid,
                                  NN, DD, D2, mlp_b1 + (size_t)l * D2,
                                  nullptr, nullptr, nullptr, nullptr, 0);
        }
        // z = BN(hidden @ W2 + b2)  (+ReLU unless last layer)
        {
            float* zdst = (l == LL - 1) ? out : p_h;
            int mode = (l == LL - 1) ? 2 : 1;
            dim3 grid((DD + BN - 1) / BN, (NN + BM - 1) / BM);
            k_gemm<<<grid, 256>>>(p_hid, mlp_w2 + (size_t)l * D2 * DD, zdst,
                                  NN, D2, DD, mlp_b2 + (size_t)l * DD,
                                  bng + (size_t)l * DD, bnb + (size_t)l * DD,
                                  bnm + (size_t)l * DD, bnv + (size_t)l * DD, mode);
        }

        if (l < LL - 1) {
            // pooled mean + virtual node update
            k_zero<<<bGD, TPB>>>(p_pool, GD);
            k_pool<<<(NN + 3) / 4, 128>>>(p_h, batch, p_pool, NN);
            k_vn<<<GG, 512>>>(p_vn, p_pool, p_cnt,
                              vn_w1 + (size_t)l * DD * DD, vn_b1 + (size_t)l * DD,
                              vn_lng + (size_t)l * DD, vn_lnb + (size_t)l * DD,
                              vn_w2 + (size_t)l * DD * DD, vn_b2 + (size_t)l * DD);
            k_addvn<<<bElem, TPB>>>(p_h, p_vn, batch, ND);
        }
    }
}

// round 2
// speedup vs baseline: 2.2913x; 2.2913x over previous
#include <cuda_runtime.h>
#include <cuda_bf16.h>
#include <math.h>
#include <stdint.h>

#define NN 100000
#define EE 250000
#define GG 4000
#define DD 300
#define D2 600
#define LL 5
#define EPS 1e-5f

// ---------------- scratch (device globals; no allocation) ----------------
__device__ float g_h[(size_t)NN * DD];     // node state h
__device__ float g_aggr[(size_t)NN * DD];  // GIN aggregate
__device__ float g_hid[(size_t)NN * D2];   // MLP hidden
__device__ float g_pool[(size_t)GG * DD];  // pooled per-graph
__device__ float g_vn[(size_t)GG * DD];    // virtual node state
__device__ float g_cnt[GG];                // node counts per graph

// ---------------- small utility kernels ----------------
__global__ void k_zero(float* p, long n) {
    long i = (long)blockIdx.x * blockDim.x + threadIdx.x;
    if (i < n) p[i] = 0.f;
}

__global__ void k_count(const int* __restrict__ batch, float* cnt, int n) {
    int i = blockIdx.x * blockDim.x + threadIdx.x;
    if (i < n) atomicAdd(&cnt[batch[i]], 1.f);
}

__global__ void k_init_h(const int* __restrict__ x_atom, const int* __restrict__ x_chir,
                         const float* __restrict__ emb1, const float* __restrict__ emb2,
                         const float* __restrict__ vn_emb, float* __restrict__ h, long total) {
    long idx = (long)blockIdx.x * blockDim.x + threadIdx.x;
    if (idx >= total) return;
    int i = (int)(idx / DD);
    int d = (int)(idx % DD);
    h[idx] = emb1[(size_t)x_atom[i] * DD + d] + emb2[(size_t)x_chir[i] * DD + d] + vn_emb[d];
}

__global__ void k_init_vn(const float* __restrict__ vn_emb, float* __restrict__ vn, long total) {
    long idx = (long)blockIdx.x * blockDim.x + threadIdx.x;
    if (idx >= total) return;
    vn[idx] = vn_emb[idx % DD];
}

// aggr = h + selfloop_emb
__global__ void k_aggr_init(const float* __restrict__ h,
                            const float* __restrict__ e1self, const float* __restrict__ e2self,
                            float* __restrict__ aggr, long total) {
    long idx = (long)blockIdx.x * blockDim.x + threadIdx.x;
    if (idx >= total) return;
    int d = (int)(idx % DD);
    aggr[idx] = h[idx] + e1self[d] + e2self[d];
}

// one warp per edge: aggr[dst] += h[src] + e1[type] + e2[dir]
__global__ void k_scatter(const float* __restrict__ h,
                          const int* __restrict__ src, const int* __restrict__ dst,
                          const int* __restrict__ et, const int* __restrict__ ed,
                          const float* __restrict__ e1, const float* __restrict__ e2,
                          float* __restrict__ aggr, int E) {
    int warp = blockIdx.x * (blockDim.x >> 5) + (threadIdx.x >> 5);
    if (warp >= E) return;
    int lane = threadIdx.x & 31;
    int s = src[warp], t = dst[warp];
    const float* ea = e1 + (size_t)et[warp] * DD;
    const float* eb = e2 + (size_t)ed[warp] * DD;
    const float* hs = h + (size_t)s * DD;
    float* at = aggr + (size_t)t * DD;
    for (int d = lane; d < DD; d += 32)
        atomicAdd(&at[d], hs[d] + ea[d] + eb[d]);
}

// one warp per node: pool[batch[i]] += z[i]
__global__ void k_pool(const float* __restrict__ z, const int* __restrict__ batch,
                       float* __restrict__ pool, int n) {
    int warp = blockIdx.x * (blockDim.x >> 5) + (threadIdx.x >> 5);
    if (warp >= n) return;
    int lane = threadIdx.x & 31;
    int b = batch[warp];
    const float* zs = z + (size_t)warp * DD;
    float* pd = pool + (size_t)b * DD;
    for (int d = lane; d < DD; d += 32)
        atomicAdd(&pd[d], zs[d]);
}

// h[i] += vn[batch[i]]
__global__ void k_addvn(float* __restrict__ h, const float* __restrict__ vn,
                        const int* __restrict__ batch, long total) {
    long idx = (long)blockIdx.x * blockDim.x + threadIdx.x;
    if (idx >= total) return;
    int i = (int)(idx / DD);
    int d = (int)(idx % DD);
    h[idx] += vn[(size_t)batch[i] * DD + d];
}

// virtual node MLP: one block (512 threads) per graph
__global__ void k_vn(float* __restrict__ vn, const float* __restrict__ pooled,
                     const float* __restrict__ cnt,
                     const float* __restrict__ w1, const float* __restrict__ b1,
                     const float* __restrict__ lng, const float* __restrict__ lnb,
                     const float* __restrict__ w2, const float* __restrict__ b2) {
    int g = blockIdx.x;
    int tid = threadIdx.x;
    __shared__ float s_in[DD];
    __shared__ float s_t[DD];
    __shared__ float s_red[512];

    float c = fmaxf(cnt[g], 1.f);
    if (tid < DD) s_in[tid] = pooled[(size_t)g * DD + tid] / c + vn[(size_t)g * DD + tid];
    __syncthreads();

    float t = 0.f;
    if (tid < DD) {
        float acc = b1[tid];
        #pragma unroll 4
        for (int k = 0; k < DD; k++) acc = fmaf(s_in[k], w1[(size_t)k * DD + tid], acc);
        t = acc;
    }
    // mean
    s_red[tid] = (tid < DD) ? t : 0.f;
    __syncthreads();
    for (int s = 256; s > 0; s >>= 1) {
        if (tid < s) s_red[tid] += s_red[tid + s];
        __syncthreads();
    }
    float mu = s_red[0] / DD;
    __syncthreads();
    // var (population)
    float dmu = (tid < DD) ? (t - mu) : 0.f;
    s_red[tid] = dmu * dmu;
    __syncthreads();
    for (int s = 256; s > 0; s >>= 1) {
        if (tid < s) s_red[tid] += s_red[tid + s];
        __syncthreads();
    }
    float var = s_red[0] / DD;
    __syncthreads();

    if (tid < DD) {
        float x = (t - mu) * rsqrtf(var + EPS) * lng[tid] + lnb[tid];
        s_t[tid] = fmaxf(x, 0.f);
    }
    __syncthreads();

    if (tid < DD) {
        float acc = b2[tid];
        #pragma unroll 4
        for (int k = 0; k < DD; k++) acc = fmaf(s_t[k], w2[(size_t)k * DD + tid], acc);
        vn[(size_t)g * DD + tid] = acc;
    }
}

// ---------------- TF32 tensor-core GEMM with fused epilogue ----------------
// C[n,m] = epilogue( A[n,k] @ B[k,m] + bias[m] )
// mode 0: ReLU(x+bias)          (MLP hidden)
// mode 1: BN(x+bias) then ReLU  (layer output, not last)
// mode 2: BN(x+bias)            (last layer)

__device__ __forceinline__ float tf32r(float x) {
    uint32_t o;
    asm("cvt.rna.tf32.f32 %0, %1;" : "=r"(o) : "f"(x));
    return __uint_as_float(o);
}

__device__ __forceinline__ void mma_tf32(float* c, const uint32_t* a, const uint32_t* b) {
    asm volatile(
        "mma.sync.aligned.m16n8k8.row.col.f32.tf32.tf32.f32 "
        "{%0,%1,%2,%3}, {%4,%5,%6,%7}, {%8,%9}, {%0,%1,%2,%3};\n"
        : "+f"(c[0]), "+f"(c[1]), "+f"(c[2]), "+f"(c[3])
        : "r"(a[0]), "r"(a[1]), "r"(a[2]), "r"(a[3]), "r"(b[0]), "r"(b[1]));
}

#define BM 128
#define BN 64
#define BK 32
#define AST 36   // As row stride (BK+4): conflict-free fragment reads
#define BST 72   // Bs row stride (BN+8): conflict-free fragment reads

__global__ __launch_bounds__(256) void k_gemm_tf32(const float* __restrict__ A,
                                                   const float* __restrict__ B,
                                                   float* __restrict__ C,
                                                   int Nrows, int K, int M,
                                                   const float* __restrict__ bias,
                                                   const float* __restrict__ bng,
                                                   const float* __restrict__ bnb,
                                                   const float* __restrict__ bnm,
                                                   const float* __restrict__ bnv,
                                                   int mode) {
    __shared__ float As[BM * AST];  // [m][k]
    __shared__ float Bs[BK * BST];  // [k][n]

    int tid = threadIdx.x;
    int warp = tid >> 5, lane = tid & 31;
    int warp_m = warp & 3;     // 4 warps over M (32 rows each)
    int warp_n = warp >> 2;    // 2 warps over N (32 cols each)
    int row0 = blockIdx.y * BM;
    int col0 = blockIdx.x * BN;

    float acc[2][4][4];
    #pragma unroll
    for (int mt = 0; mt < 2; mt++)
        #pragma unroll
        for (int nt = 0; nt < 4; nt++)
            #pragma unroll
            for (int i = 0; i < 4; i++) acc[mt][nt][i] = 0.f;

    int lq = lane >> 2;   // lane/4
    int lr = lane & 3;    // lane%4

    for (int k0 = 0; k0 < K; k0 += BK) {
        // --- load A tile (BM x BK): 4 float4 per thread ---
        {
            int r = tid >> 3;             // 0..31
            int kq = (tid & 7) * 4;       // 0..28
            #pragma unroll
            for (int p = 0; p < 4; p++) {
                int rr = r + p * 32;
                int gr = row0 + rr, gk = k0 + kq;
                float4 v = make_float4(0.f, 0.f, 0.f, 0.f);
                if (gr < Nrows && gk < K)   // K % 4 == 0 -> full vector or none
                    v = *(const float4*)(A + (size_t)gr * K + gk);
                float* d = As + rr * AST + kq;
                d[0] = tf32r(v.x); d[1] = tf32r(v.y); d[2] = tf32r(v.z); d[3] = tf32r(v.w);
            }
        }
        // --- load B tile (BK x BN): 2 float4 per thread ---
        {
            int kk = tid >> 4;            // 0..15
            int nq = (tid & 15) * 4;      // 0..60
            #pragma unroll
            for (int p = 0; p < 2; p++) {
                int kr = kk + p * 16;
                int gk = k0 + kr, gc = col0 + nq;
                float4 v = make_float4(0.f, 0.f, 0.f, 0.f);
                if (gk < K && gc < M)       // M % 4 == 0 -> full vector or none
                    v = *(const float4*)(B + (size_t)gk * M + gc);
                float* d = Bs + kr * BST + nq;
                d[0] = tf32r(v.x); d[1] = tf32r(v.y); d[2] = tf32r(v.z); d[3] = tf32r(v.w);
            }
        }
        __syncthreads();

        #pragma unroll
        for (int ks = 0; ks < 4; ks++) {
            int k8 = ks * 8;
            uint32_t af[2][4], bf[4][2];
            int ar = warp_m * 32 + lq;
            int ac = k8 + lr;
            #pragma unroll
            for (int mt = 0; mt < 2; mt++) {
                const float* base = As + (ar + mt * 16) * AST + ac;
                af[mt][0] = __float_as_uint(base[0]);
                af[mt][1] = __float_as_uint(base[8 * AST]);
                af[mt][2] = __float_as_uint(base[4]);
                af[mt][3] = __float_as_uint(base[8 * AST + 4]);
            }
            int bc = warp_n * 32 + lq;
            #pragma unroll
            for (int nt = 0; nt < 4; nt++) {
                const float* base = Bs + (k8 + lr) * BST + bc + nt * 8;
                bf[nt][0] = __float_as_uint(base[0]);
                bf[nt][1] = __float_as_uint(base[4 * BST]);
            }
            #pragma unroll
            for (int mt = 0; mt < 2; mt++)
                #pragma unroll
                for (int nt = 0; nt < 4; nt++)
                    mma_tf32(acc[mt][nt], af[mt], bf[nt]);
        }
        __syncthreads();
    }

    // --- epilogue ---
    #pragma unroll
    for (int mt = 0; mt < 2; mt++) {
        #pragma unroll
        for (int nt = 0; nt < 4; nt++) {
            #pragma unroll
            for (int i = 0; i < 4; i++) {
                int row = row0 + warp_m * 32 + mt * 16 + lq + (i >= 2 ? 8 : 0);
                int col = col0 + warp_n * 32 + nt * 8 + lr * 2 + (i & 1);
                if (row >= Nrows || col >= M) continue;
                float v = acc[mt][nt][i] + bias[col];
                if (mode == 0) {
                    v = fmaxf(v, 0.f);
                } else {
                    float sc = bng[col] * rsqrtf(bnv[col] + EPS);
                    v = (v - bnm[col]) * sc + bnb[col];
                    if (mode == 1) v = fmaxf(v, 0.f);
                }
                C[(size_t)row * M + col] = v;
            }
        }
    }
}

// ---------------- launch ----------------
extern "C" void kernel_launch(void* const* d_in, const int* in_sizes, int n_in,
                              void* d_out, int out_size) {
    const int*   x_atom  = (const int*)d_in[0];
    const int*   x_chir  = (const int*)d_in[1];
    const int*   src     = (const int*)d_in[2];
    const int*   dst     = (const int*)d_in[3];
    const int*   etype   = (const int*)d_in[4];
    const int*   edir    = (const int*)d_in[5];
    const int*   batch   = (const int*)d_in[6];
    const float* x_emb1  = (const float*)d_in[7];
    const float* x_emb2  = (const float*)d_in[8];
    const float* edge_e1 = (const float*)d_in[9];    // [L,6,D]
    const float* edge_e2 = (const float*)d_in[10];   // [L,3,D]
    const float* mlp_w1  = (const float*)d_in[11];   // [L,D,2D]
    const float* mlp_b1  = (const float*)d_in[12];   // [L,2D]
    const float* mlp_w2  = (const float*)d_in[13];   // [L,2D,D]
    const float* mlp_b2  = (const float*)d_in[14];   // [L,D]
    const float* bng     = (const float*)d_in[15];
    const float* bnb     = (const float*)d_in[16];
    const float* bnm     = (const float*)d_in[17];
    const float* bnv     = (const float*)d_in[18];
    const float* vn_emb  = (const float*)d_in[19];
    const float* vn_w1   = (const float*)d_in[20];   // [L-1,D,D]
    const float* vn_b1   = (const float*)d_in[21];
    const float* vn_lng  = (const float*)d_in[22];
    const float* vn_lnb  = (const float*)d_in[23];
    const float* vn_w2   = (const float*)d_in[24];
    const float* vn_b2   = (const float*)d_in[25];
    float* out = (float*)d_out;

    float *p_h, *p_aggr, *p_hid, *p_pool, *p_vn, *p_cnt;
    cudaGetSymbolAddress((void**)&p_h, g_h);
    cudaGetSymbolAddress((void**)&p_aggr, g_aggr);
    cudaGetSymbolAddress((void**)&p_hid, g_hid);
    cudaGetSymbolAddress((void**)&p_pool, g_pool);
    cudaGetSymbolAddress((void**)&p_vn, g_vn);
    cudaGetSymbolAddress((void**)&p_cnt, g_cnt);

    const long ND = (long)NN * DD;
    const long GD = (long)GG * DD;
    const int TPB = 256;
    dim3 bElem((unsigned)((ND + TPB - 1) / TPB));
    dim3 bGD((unsigned)((GD + TPB - 1) / TPB));

    // counts
    k_zero<<<(GG + TPB - 1) / TPB, TPB>>>(p_cnt, GG);
    k_count<<<(NN + TPB - 1) / TPB, TPB>>>(batch, p_cnt, NN);

    // h0 and vn0
    k_init_h<<<bElem, TPB>>>(x_atom, x_chir, x_emb1, x_emb2, vn_emb, p_h, ND);
    k_init_vn<<<bGD, TPB>>>(vn_emb, p_vn, GD);

    for (int l = 0; l < LL; l++) {
        const float* e1l = edge_e1 + (size_t)l * 6 * DD;
        const float* e2l = edge_e2 + (size_t)l * 3 * DD;
        const float* e1self = e1l + 4 * DD;
        const float* e2self = e2l;  // dir 0

        // aggr = h + selfloop
        k_aggr_init<<<bElem, TPB>>>(p_h, e1self, e2self, p_aggr, ND);
        // scatter messages
        k_scatter<<<(EE + 3) / 4, 128>>>(p_h, src, dst, etype, edir, e1l, e2l, p_aggr, EE);

        // hidden = ReLU(aggr @ W1 + b1)   [N, 600]
        {
            dim3 grid((D2 + BN - 1) / BN, (NN + BM - 1) / BM);
            k_gemm_tf32<<<grid, 256>>>(p_aggr, mlp_w1 + (size_t)l * DD * D2, p_hid,
                                       NN, DD, D2, mlp_b1 + (size_t)l * D2,
                                       nullptr, nullptr, nullptr, nullptr, 0);
        }
        // z = BN(hidden @ W2 + b2)  (+ReLU unless last layer)
        {
            float* zdst = (l == LL - 1) ? out : p_h;
            int mode = (l == LL - 1) ? 2 : 1;
            dim3 grid((DD + BN - 1) / BN, (NN + BM - 1) / BM);
            k_gemm_tf32<<<grid, 256>>>(p_hid, mlp_w2 + (size_t)l * D2 * DD, zdst,
                                       NN, D2, DD, mlp_b2 + (size_t)l * DD,
                                       bng + (size_t)l * DD, bnb + (size_t)l * DD,
                                       bnm + (size_t)l * DD, bnv + (size_t)l * DD, mode);
        }

        if (l < LL - 1) {
            // pooled mean + virtual node update
            k_zero<<<bGD, TPB>>>(p_pool, GD);
            k_pool<<<(NN + 3) / 4, 128>>>(p_h, batch, p_pool, NN);
            k_vn<<<GG, 512>>>(p_vn, p_pool, p_cnt,
                              vn_w1 + (size_t)l * DD * DD, vn_b1 + (size_t)l * DD,
                              vn_lng + (size_t)l * DD, vn_lnb + (size_t)l * DD,
                              vn_w2 + (size_t)l * DD * DD, vn_b2 + (size_t)l * DD);
            k_addvn<<<bElem, TPB>>>(p_h, p_vn, batch, ND);
        }
    }
}

// round 3
// speedup vs baseline: 2.6794x; 1.1694x over previous
#include <cuda_runtime.h>
#include <cuda_bf16.h>
#include <math.h>
#include <stdint.h>

#define NN 100000
#define EE 250000
#define GG 4000
#define DD 300
#define D2 600
#define LL 5
#define EPS 1e-5f

// ---------------- scratch (device globals; no allocation) ----------------
__device__ float g_h[(size_t)NN * DD];     // node state h
__device__ float g_aggr[(size_t)NN * DD];  // GIN aggregate
__device__ float g_hid[(size_t)NN * D2];   // MLP hidden
__device__ float g_pool[(size_t)GG * DD];  // pooled per-graph
__device__ float g_vn[(size_t)GG * DD];    // virtual node state
__device__ float g_vnin[(size_t)GG * DD];  // vn mlp input
__device__ float g_vnt[(size_t)GG * DD];   // vn mlp hidden
__device__ float g_cnt[GG];                // node counts per graph
// tf32-rounded weights
__device__ float g_w1r[(size_t)LL * DD * D2];
__device__ float g_w2r[(size_t)LL * D2 * DD];
__device__ float g_vw1r[(size_t)(LL - 1) * DD * DD];
__device__ float g_vw2r[(size_t)(LL - 1) * DD * DD];

__device__ __forceinline__ float tf32r(float x) {
    uint32_t o;
    asm("cvt.rna.tf32.f32 %0, %1;" : "=r"(o) : "f"(x));
    return __uint_as_float(o);
}
__device__ __forceinline__ uint32_t tf32u(float x) {
    uint32_t o;
    asm("cvt.rna.tf32.f32 %0, %1;" : "=r"(o) : "f"(x));
    return o;
}

// ---------------- small utility kernels ----------------
__global__ void k_zero(float* p, long n) {
    long i = (long)blockIdx.x * blockDim.x + threadIdx.x;
    if (i < n) p[i] = 0.f;
}

__global__ void k_round(const float* __restrict__ s, float* __restrict__ d, long n) {
    long i = (long)blockIdx.x * blockDim.x + threadIdx.x;
    if (i < n) d[i] = tf32r(s[i]);
}

__global__ void k_count(const int* __restrict__ batch, float* cnt, int n) {
    int i = blockIdx.x * blockDim.x + threadIdx.x;
    if (i < n) atomicAdd(&cnt[batch[i]], 1.f);
}

__global__ void k_init_h(const int* __restrict__ x_atom, const int* __restrict__ x_chir,
                         const float* __restrict__ emb1, const float* __restrict__ emb2,
                         const float* __restrict__ vn_emb, float* __restrict__ h, long total) {
    long idx = (long)blockIdx.x * blockDim.x + threadIdx.x;
    if (idx >= total) return;
    int i = (int)(idx / DD);
    int d = (int)(idx % DD);
    h[idx] = emb1[(size_t)x_atom[i] * DD + d] + emb2[(size_t)x_chir[i] * DD + d] + vn_emb[d];
}

__global__ void k_init_vn(const float* __restrict__ vn_emb, float* __restrict__ vn, long total) {
    long idx = (long)blockIdx.x * blockDim.x + threadIdx.x;
    if (idx >= total) return;
    vn[idx] = vn_emb[idx % DD];
}

// aggr = h + selfloop_emb
__global__ void k_aggr_init(const float* __restrict__ h,
                            const float* __restrict__ e1self, const float* __restrict__ e2self,
                            float* __restrict__ aggr, long total) {
    long idx = (long)blockIdx.x * blockDim.x + threadIdx.x;
    if (idx >= total) return;
    int d = (int)(idx % DD);
    aggr[idx] = h[idx] + e1self[d] + e2self[d];
}

// one warp per edge: aggr[dst] += h[src] + e1[type] + e2[dir]
__global__ void k_scatter(const float* __restrict__ h,
                          const int* __restrict__ src, const int* __restrict__ dst,
                          const int* __restrict__ et, const int* __restrict__ ed,
                          const float* __restrict__ e1, const float* __restrict__ e2,
                          float* __restrict__ aggr, int E) {
    int warp = blockIdx.x * (blockDim.x >> 5) + (threadIdx.x >> 5);
    if (warp >= E) return;
    int lane = threadIdx.x & 31;
    int s = src[warp], t = dst[warp];
    const float* ea = e1 + (size_t)et[warp] * DD;
    const float* eb = e2 + (size_t)ed[warp] * DD;
    const float* hs = h + (size_t)s * DD;
    float* at = aggr + (size_t)t * DD;
    for (int d = lane; d < DD; d += 32)
        atomicAdd(&at[d], hs[d] + ea[d] + eb[d]);
}

// one warp per node: pool[batch[i]] += z[i]
__global__ void k_pool(const float* __restrict__ z, const int* __restrict__ batch,
                       float* __restrict__ pool, int n) {
    int warp = blockIdx.x * (blockDim.x >> 5) + (threadIdx.x >> 5);
    if (warp >= n) return;
    int lane = threadIdx.x & 31;
    int b = batch[warp];
    const float* zs = z + (size_t)warp * DD;
    float* pd = pool + (size_t)b * DD;
    for (int d = lane; d < DD; d += 32)
        atomicAdd(&pd[d], zs[d]);
}

// h[i] += vn[batch[i]]
__global__ void k_addvn(float* __restrict__ h, const float* __restrict__ vn,
                        const int* __restrict__ batch, long total) {
    long idx = (long)blockIdx.x * blockDim.x + threadIdx.x;
    if (idx >= total) return;
    int i = (int)(idx / DD);
    int d = (int)(idx % DD);
    h[idx] += vn[(size_t)batch[i] * DD + d];
}

// vn_in = pooled/cnt + vn
__global__ void k_vnprep(const float* __restrict__ pooled, const float* __restrict__ cnt,
                         const float* __restrict__ vn, float* __restrict__ out, long total) {
    long idx = (long)blockIdx.x * blockDim.x + threadIdx.x;
    if (idx >= total) return;
    int g = (int)(idx / DD);
    out[idx] = pooled[idx] / fmaxf(cnt[g], 1.f) + vn[idx];
}

// LayerNorm + ReLU over rows of [GG x DD], in place. block=128, grid=GG
__global__ void k_ln(float* __restrict__ t, const float* __restrict__ g,
                     const float* __restrict__ b) {
    int gid = blockIdx.x;
    int tid = threadIdx.x;
    float* row = t + (size_t)gid * DD;
    float v[3];
    float s = 0.f;
    #pragma unroll
    for (int i = 0; i < 3; i++) {
        int d = tid + i * 128;
        v[i] = (d < DD) ? row[d] : 0.f;
        s += v[i];
    }
    __shared__ float red[4];
    __shared__ float red2[4];
    for (int o = 16; o; o >>= 1) s += __shfl_xor_sync(~0u, s, o);
    if ((tid & 31) == 0) red[tid >> 5] = s;
    __syncthreads();
    s = red[0] + red[1] + red[2] + red[3];
    float mu = s / DD;
    float q = 0.f;
    #pragma unroll
    for (int i = 0; i < 3; i++) {
        int d = tid + i * 128;
        float dv = (d < DD) ? (v[i] - mu) : 0.f;
        q += dv * dv;
    }
    for (int o = 16; o; o >>= 1) q += __shfl_xor_sync(~0u, q, o);
    if ((tid & 31) == 0) red2[tid >> 5] = q;
    __syncthreads();
    q = red2[0] + red2[1] + red2[2] + red2[3];
    float rs = rsqrtf(q / DD + EPS);
    #pragma unroll
    for (int i = 0; i < 3; i++) {
        int d = tid + i * 128;
        if (d < DD) {
            float x = (v[i] - mu) * rs * g[d] + b[d];
            row[d] = fmaxf(x, 0.f);
        }
    }
}

// ---------------- TF32 tensor-core GEMM, cp.async double-buffered ----------------
// C[n,m] = epilogue( A[n,k] @ B[k,m] + bias[m] )
// mode 0: ReLU(x+bias); 1: BN then ReLU; 2: BN; 3: bias only
// B must be pre-rounded to tf32. A rounded per-fragment.

__device__ __forceinline__ void mma_tf32(float* c, const uint32_t* a, const uint32_t* b) {
    asm volatile(
        "mma.sync.aligned.m16n8k8.row.col.f32.tf32.tf32.f32 "
        "{%0,%1,%2,%3}, {%4,%5,%6,%7}, {%8,%9}, {%0,%1,%2,%3};\n"
        : "+f"(c[0]), "+f"(c[1]), "+f"(c[2]), "+f"(c[3])
        : "r"(a[0]), "r"(a[1]), "r"(a[2]), "r"(a[3]), "r"(b[0]), "r"(b[1]));
}

#define BM 128
#define BN 64
#define BK 32
#define AST 36   // As row stride (BK+4): conflict-free & 16B-aligned rows
#define BST 72   // Bs row stride (BN+8)

__global__ __launch_bounds__(256) void k_gemm_tf32(const float* __restrict__ A,
                                                   const float* __restrict__ B,
                                                   float* __restrict__ C,
                                                   int Nrows, int K, int M,
                                                   const float* __restrict__ bias,
                                                   const float* __restrict__ bng,
                                                   const float* __restrict__ bnb,
                                                   const float* __restrict__ bnm,
                                                   const float* __restrict__ bnv,
                                                   int mode) {
    __shared__ float As[2][BM * AST];
    __shared__ float Bs[2][BK * BST];

    int tid = threadIdx.x;
    int warp = tid >> 5, lane = tid & 31;
    int warp_m = warp & 3;
    int warp_n = warp >> 2;
    int row0 = blockIdx.y * BM;
    int col0 = blockIdx.x * BN;
    int lq = lane >> 2, lr = lane & 3;

    float acc[2][4][4] = {};

    int ra = tid >> 3;            // A: row 0..31 (+32p)
    int kq = (tid & 7) * 4;       // A: k offset
    int kb = tid >> 4;            // B: k row 0..15 (+16p)
    int nq = (tid & 15) * 4;      // B: n offset
    int nT = (K + BK - 1) / BK;

    // --- prologue: load tile 0 ---
    {
        int k0 = 0;
        #pragma unroll
        for (int p = 0; p < 4; p++) {
            int rr = ra + p * 32;
            int gr = row0 + rr, gk = k0 + kq;
            bool ok = (gr < Nrows && gk < K);
            unsigned d = (unsigned)__cvta_generic_to_shared(&As[0][rr * AST + kq]);
            const float* s = ok ? (A + (size_t)gr * K + gk) : A;
            int sz = ok ? 16 : 0;
            asm volatile("cp.async.ca.shared.global [%0], [%1], 16, %2;\n" :: "r"(d), "l"(s), "r"(sz));
        }
        #pragma unroll
        for (int p = 0; p < 2; p++) {
            int kr = kb + p * 16;
            int gk = k0 + kr, gc = col0 + nq;
            bool ok = (gk < K && gc < M);
            unsigned d = (unsigned)__cvta_generic_to_shared(&Bs[0][kr * BST + nq]);
            const float* s = ok ? (B + (size_t)gk * M + gc) : B;
            int sz = ok ? 16 : 0;
            asm volatile("cp.async.ca.shared.global [%0], [%1], 16, %2;\n" :: "r"(d), "l"(s), "r"(sz));
        }
        asm volatile("cp.async.commit_group;\n");
    }

    for (int t = 0; t < nT; t++) {
        asm volatile("cp.async.wait_group 0;\n");
        __syncthreads();
        // prefetch next tile into other buffer
        if (t + 1 < nT) {
            int k0 = (t + 1) * BK;
            int buf = (t + 1) & 1;
            #pragma unroll
            for (int p = 0; p < 4; p++) {
                int rr = ra + p * 32;
                int gr = row0 + rr, gk = k0 + kq;
                bool ok = (gr < Nrows && gk < K);
                unsigned d = (unsigned)__cvta_generic_to_shared(&As[buf][rr * AST + kq]);
                const float* s = ok ? (A + (size_t)gr * K + gk) : A;
                int sz = ok ? 16 : 0;
                asm volatile("cp.async.ca.shared.global [%0], [%1], 16, %2;\n" :: "r"(d), "l"(s), "r"(sz));
            }
            #pragma unroll
            for (int p = 0; p < 2; p++) {
                int kr = kb + p * 16;
                int gk = k0 + kr, gc = col0 + nq;
                bool ok = (gk < K && gc < M);
                unsigned d = (unsigned)__cvta_generic_to_shared(&Bs[buf][kr * BST + nq]);
                const float* s = ok ? (B + (size_t)gk * M + gc) : B;
                int sz = ok ? 16 : 0;
                asm volatile("cp.async.ca.shared.global [%0], [%1], 16, %2;\n" :: "r"(d), "l"(s), "r"(sz));
            }
            asm volatile("cp.async.commit_group;\n");
        }

        const float* Asb = As[t & 1];
        const float* Bsb = Bs[t & 1];
        #pragma unroll
        for (int ks = 0; ks < 4; ks++) {
            int k8 = ks * 8;
            uint32_t af[2][4], bf[4][2];
            int ar = warp_m * 32 + lq;
            int ac = k8 + lr;
            #pragma unroll
            for (int mt = 0; mt < 2; mt++) {
                const float* base = Asb + (ar + mt * 16) * AST + ac;
                af[mt][0] = tf32u(base[0]);
                af[mt][1] = tf32u(base[8 * AST]);
                af[mt][2] = tf32u(base[4]);
                af[mt][3] = tf32u(base[8 * AST + 4]);
            }
            int bc = warp_n * 32 + lq;
            #pragma unroll
            for (int nt = 0; nt < 4; nt++) {
                const float* base = Bsb + (k8 + lr) * BST + bc + nt * 8;
                bf[nt][0] = __float_as_uint(base[0]);
                bf[nt][1] = __float_as_uint(base[4 * BST]);
            }
            #pragma unroll
            for (int mt = 0; mt < 2; mt++)
                #pragma unroll
                for (int nt = 0; nt < 4; nt++)
                    mma_tf32(acc[mt][nt], af[mt], bf[nt]);
        }
        __syncthreads();
    }

    // --- epilogue ---
    #pragma unroll
    for (int mt = 0; mt < 2; mt++) {
        #pragma unroll
        for (int nt = 0; nt < 4; nt++) {
            #pragma unroll
            for (int i = 0; i < 4; i++) {
                int row = row0 + warp_m * 32 + mt * 16 + lq + (i >= 2 ? 8 : 0);
                int col = col0 + warp_n * 32 + nt * 8 + lr * 2 + (i & 1);
                if (row >= Nrows || col >= M) continue;
                float v = acc[mt][nt][i] + bias[col];
                if (mode == 0) {
                    v = fmaxf(v, 0.f);
                } else if (mode != 3) {
                    float sc = bng[col] * rsqrtf(bnv[col] + EPS);
                    v = (v - bnm[col]) * sc + bnb[col];
                    if (mode == 1) v = fmaxf(v, 0.f);
                }
                C[(size_t)row * M + col] = v;
            }
        }
    }
}

// ---------------- launch ----------------
extern "C" void kernel_launch(void* const* d_in, const int* in_sizes, int n_in,
                              void* d_out, int out_size) {
    const int*   x_atom  = (const int*)d_in[0];
    const int*   x_chir  = (const int*)d_in[1];
    const int*   src     = (const int*)d_in[2];
    const int*   dst     = (const int*)d_in[3];
    const int*   etype   = (const int*)d_in[4];
    const int*   edir    = (const int*)d_in[5];
    const int*   batch   = (const int*)d_in[6];
    const float* x_emb1  = (const float*)d_in[7];
    const float* x_emb2  = (const float*)d_in[8];
    const float* edge_e1 = (const float*)d_in[9];    // [L,6,D]
    const float* edge_e2 = (const float*)d_in[10];   // [L,3,D]
    const float* mlp_w1  = (const float*)d_in[11];   // [L,D,2D]
    const float* mlp_b1  = (const float*)d_in[12];   // [L,2D]
    const float* mlp_w2  = (const float*)d_in[13];   // [L,2D,D]
    const float* mlp_b2  = (const float*)d_in[14];   // [L,D]
    const float* bng     = (const float*)d_in[15];
    const float* bnb     = (const float*)d_in[16];
    const float* bnm     = (const float*)d_in[17];
    const float* bnv     = (const float*)d_in[18];
    const float* vn_emb  = (const float*)d_in[19];
    const float* vn_w1   = (const float*)d_in[20];   // [L-1,D,D]
    const float* vn_b1   = (const float*)d_in[21];
    const float* vn_lng  = (const float*)d_in[22];
    const float* vn_lnb  = (const float*)d_in[23];
    const float* vn_w2   = (const float*)d_in[24];
    const float* vn_b2   = (const float*)d_in[25];
    float* out = (float*)d_out;

    float *p_h, *p_aggr, *p_hid, *p_pool, *p_vn, *p_vnin, *p_vnt, *p_cnt;
    float *p_w1r, *p_w2r, *p_vw1r, *p_vw2r;
    cudaGetSymbolAddress((void**)&p_h, g_h);
    cudaGetSymbolAddress((void**)&p_aggr, g_aggr);
    cudaGetSymbolAddress((void**)&p_hid, g_hid);
    cudaGetSymbolAddress((void**)&p_pool, g_pool);
    cudaGetSymbolAddress((void**)&p_vn, g_vn);
    cudaGetSymbolAddress((void**)&p_vnin, g_vnin);
    cudaGetSymbolAddress((void**)&p_vnt, g_vnt);
    cudaGetSymbolAddress((void**)&p_cnt, g_cnt);
    cudaGetSymbolAddress((void**)&p_w1r, g_w1r);
    cudaGetSymbolAddress((void**)&p_w2r, g_w2r);
    cudaGetSymbolAddress((void**)&p_vw1r, g_vw1r);
    cudaGetSymbolAddress((void**)&p_vw2r, g_vw2r);

    const long ND = (long)NN * DD;
    const long GD = (long)GG * DD;
    const int TPB = 256;
    dim3 bElem((unsigned)((ND + TPB - 1) / TPB));
    dim3 bGD((unsigned)((GD + TPB - 1) / TPB));

    // pre-round weights to tf32 (B operands)
    {
        long n1 = (long)LL * DD * D2;
        long n2 = (long)LL * D2 * DD;
        long n3 = (long)(LL - 1) * DD * DD;
        k_round<<<(unsigned)((n1 + TPB - 1) / TPB), TPB>>>(mlp_w1, p_w1r, n1);
        k_round<<<(unsigned)((n2 + TPB - 1) / TPB), TPB>>>(mlp_w2, p_w2r, n2);
        k_round<<<(unsigned)((n3 + TPB - 1) / TPB), TPB>>>(vn_w1, p_vw1r, n3);
        k_round<<<(unsigned)((n3 + TPB - 1) / TPB), TPB>>>(vn_w2, p_vw2r, n3);
    }

    // counts
    k_zero<<<(GG + TPB - 1) / TPB, TPB>>>(p_cnt, GG);
    k_count<<<(NN + TPB - 1) / TPB, TPB>>>(batch, p_cnt, NN);

    // h0 and vn0
    k_init_h<<<bElem, TPB>>>(x_atom, x_chir, x_emb1, x_emb2, vn_emb, p_h, ND);
    k_init_vn<<<bGD, TPB>>>(vn_emb, p_vn, GD);

    for (int l = 0; l < LL; l++) {
        const float* e1l = edge_e1 + (size_t)l * 6 * DD;
        const float* e2l = edge_e2 + (size_t)l * 3 * DD;
        const float* e1self = e1l + 4 * DD;
        const float* e2self = e2l;  // dir 0

        k_aggr_init<<<bElem, TPB>>>(p_h, e1self, e2self, p_aggr, ND);
        k_scatter<<<(EE + 3) / 4, 128>>>(p_h, src, dst, etype, edir, e1l, e2l, p_aggr, EE);

        // hidden = ReLU(aggr @ W1 + b1)   [N, 600]
        {
            dim3 grid((D2 + BN - 1) / BN, (NN + BM - 1) / BM);
            k_gemm_tf32<<<grid, 256>>>(p_aggr, p_w1r + (size_t)l * DD * D2, p_hid,
                                       NN, DD, D2, mlp_b1 + (size_t)l * D2,
                                       nullptr, nullptr, nullptr, nullptr, 0);
        }
        // z = BN(hidden @ W2 + b2)  (+ReLU unless last layer)
        {
            float* zdst = (l == LL - 1) ? out : p_h;
            int mode = (l == LL - 1) ? 2 : 1;
            dim3 grid((DD + BN - 1) / BN, (NN + BM - 1) / BM);
            k_gemm_tf32<<<grid, 256>>>(p_hid, p_w2r + (size_t)l * D2 * DD, zdst,
                                       NN, D2, DD, mlp_b2 + (size_t)l * DD,
                                       bng + (size_t)l * DD, bnb + (size_t)l * DD,
                                       bnm + (size_t)l * DD, bnv + (size_t)l * DD, mode);
        }

        if (l < LL - 1) {
            // pooled mean + virtual node update (GEMM-based)
            k_zero<<<bGD, TPB>>>(p_pool, GD);
            k_pool<<<(NN + 3) / 4, 128>>>(p_h, batch, p_pool, NN);
            k_vnprep<<<bGD, TPB>>>(p_pool, p_cnt, p_vn, p_vnin, GD);
            {
                dim3 grid((DD + BN - 1) / BN, (GG + BM - 1) / BM);
                k_gemm_tf32<<<grid, 256>>>(p_vnin, p_vw1r + (size_t)l * DD * DD, p_vnt,
                                           GG, DD, DD, vn_b1 + (size_t)l * DD,
                                           nullptr, nullptr, nullptr, nullptr, 3);
            }
            k_ln<<<GG, 128>>>(p_vnt, vn_lng + (size_t)l * DD, vn_lnb + (size_t)l * DD);
            {
                dim3 grid((DD + BN - 1) / BN, (GG + BM - 1) / BM);
                k_gemm_tf32<<<grid, 256>>>(p_vnt, p_vw2r + (size_t)l * DD * DD, p_vn,
                                           GG, DD, DD, vn_b2 + (size_t)l * DD,
                                           nullptr, nullptr, nullptr, nullptr, 3);
            }
            k_addvn<<<bElem, TPB>>>(p_h, p_vn, batch, ND);
        }
    }
}

// round 4
// speedup vs baseline: 3.0072x; 1.1223x over previous
#include <cuda_runtime.h>
#include <cuda_bf16.h>
#include <math.h>
#include <stdint.h>

#define NN 100000
#define EE 250000
#define GG 4000
#define DD 300
#define D2 600
#define LL 5
#define EPS 1e-5f

// ---------------- scratch (device globals; no allocation) ----------------
__device__ float g_h[(size_t)NN * DD];
__device__ float g_aggr[(size_t)NN * DD];
__device__ float g_hid[(size_t)NN * D2];
__device__ float g_pool[(size_t)GG * DD];
__device__ float g_vn[(size_t)GG * DD];
__device__ float g_vnin[(size_t)GG * DD];
__device__ float g_vnt[(size_t)GG * DD];
__device__ float g_cnt[GG];
__device__ int   g_tc[(size_t)NN * 6];   // per-node incoming edge-type counts
__device__ int   g_dc[(size_t)NN * 3];   // per-node incoming edge-dir counts
// tf32-rounded weights
__device__ float g_w1r[(size_t)LL * DD * D2];
__device__ float g_w2r[(size_t)LL * D2 * DD];
__device__ float g_vw1r[(size_t)(LL - 1) * DD * DD];
__device__ float g_vw2r[(size_t)(LL - 1) * DD * DD];

__device__ __forceinline__ float tf32r(float x) {
    uint32_t o;
    asm("cvt.rna.tf32.f32 %0, %1;" : "=r"(o) : "f"(x));
    return __uint_as_float(o);
}
__device__ __forceinline__ uint32_t tf32u(float x) {
    uint32_t o;
    asm("cvt.rna.tf32.f32 %0, %1;" : "=r"(o) : "f"(x));
    return o;
}

// ---------------- small utility kernels ----------------
__global__ void k_zero(float* p, long n) {
    long i = (long)blockIdx.x * blockDim.x + threadIdx.x;
    if (i < n) p[i] = 0.f;
}
__global__ void k_zeroi(int* p, long n) {
    long i = (long)blockIdx.x * blockDim.x + threadIdx.x;
    if (i < n) p[i] = 0;
}

__global__ void k_round(const float* __restrict__ s, float* __restrict__ d, long n) {
    long i = (long)blockIdx.x * blockDim.x + threadIdx.x;
    if (i < n) d[i] = tf32r(s[i]);
}

__global__ void k_count(const int* __restrict__ batch, float* cnt, int n) {
    int i = blockIdx.x * blockDim.x + threadIdx.x;
    if (i < n) atomicAdd(&cnt[batch[i]], 1.f);
}

// histogram of incoming edge types/dirs per node (topology fixed across layers)
__global__ void k_edgehist(const int* __restrict__ dst, const int* __restrict__ et,
                           const int* __restrict__ ed, int* __restrict__ tc,
                           int* __restrict__ dc, int E) {
    int i = blockIdx.x * blockDim.x + threadIdx.x;
    if (i >= E) return;
    int t = dst[i];
    atomicAdd(&tc[(size_t)t * 6 + et[i]], 1);
    atomicAdd(&dc[(size_t)t * 3 + ed[i]], 1);
}

__global__ void k_init_h(const int* __restrict__ x_atom, const int* __restrict__ x_chir,
                         const float* __restrict__ emb1, const float* __restrict__ emb2,
                         const float* __restrict__ vn_emb, float* __restrict__ h, long total) {
    long idx = (long)blockIdx.x * blockDim.x + threadIdx.x;
    if (idx >= total) return;
    int i = (int)(idx / DD);
    int d = (int)(idx % DD);
    h[idx] = emb1[(size_t)x_atom[i] * DD + d] + emb2[(size_t)x_chir[i] * DD + d] + vn_emb[d];
}

__global__ void k_init_vn(const float* __restrict__ vn_emb, float* __restrict__ vn, long total) {
    long idx = (long)blockIdx.x * blockDim.x + threadIdx.x;
    if (idx >= total) return;
    vn[idx] = vn_emb[idx % DD];
}

// warp per node: aggr = h + selfloop + sum_t tc[t]*e1[t] + sum_u dc[u]*e2[u]
__global__ void k_aggr_init(const float* __restrict__ h,
                            const float* __restrict__ e1l, const float* __restrict__ e2l,
                            const int* __restrict__ tc, const int* __restrict__ dc,
                            float* __restrict__ aggr, int n) {
    int node = blockIdx.x * (blockDim.x >> 5) + (threadIdx.x >> 5);
    if (node >= n) return;
    int lane = threadIdx.x & 31;
    float ct[6], cd[3];
    #pragma unroll
    for (int t = 0; t < 6; t++) ct[t] = (float)tc[(size_t)node * 6 + t];
    #pragma unroll
    for (int u = 0; u < 3; u++) cd[u] = (float)dc[(size_t)node * 3 + u];
    ct[4] += 1.f;  // self loop: type 4
    cd[0] += 1.f;  // self loop: dir 0
    const float* hs = h + (size_t)node * DD;
    float* as = aggr + (size_t)node * DD;
    for (int d = lane; d < DD; d += 32) {
        float v = hs[d];
        #pragma unroll
        for (int t = 0; t < 6; t++) v = fmaf(ct[t], e1l[t * DD + d], v);
        #pragma unroll
        for (int u = 0; u < 3; u++) v = fmaf(cd[u], e2l[u * DD + d], v);
        as[d] = v;
    }
}

// warp per edge: aggr[dst] += h[src]
__global__ void k_scatter(const float* __restrict__ h,
                          const int* __restrict__ src, const int* __restrict__ dst,
                          float* __restrict__ aggr, int E) {
    int e = blockIdx.x * (blockDim.x >> 5) + (threadIdx.x >> 5);
    if (e >= E) return;
    int lane = threadIdx.x & 31;
    const float* hs = h + (size_t)src[e] * DD;
    float* at = aggr + (size_t)dst[e] * DD;
    for (int d = lane; d < DD; d += 32)
        atomicAdd(&at[d], hs[d]);
}

// h[i] += vn[batch[i]]
__global__ void k_addvn(float* __restrict__ h, const float* __restrict__ vn,
                        const int* __restrict__ batch, long total) {
    long idx = (long)blockIdx.x * blockDim.x + threadIdx.x;
    if (idx >= total) return;
    int i = (int)(idx / DD);
    int d = (int)(idx % DD);
    h[idx] += vn[(size_t)batch[i] * DD + d];
}

// vn_in = pooled/cnt + vn
__global__ void k_vnprep(const float* __restrict__ pooled, const float* __restrict__ cnt,
                         const float* __restrict__ vn, float* __restrict__ out, long total) {
    long idx = (long)blockIdx.x * blockDim.x + threadIdx.x;
    if (idx >= total) return;
    int g = (int)(idx / DD);
    out[idx] = pooled[idx] / fmaxf(cnt[g], 1.f) + vn[idx];
}

// LayerNorm + ReLU over rows of [GG x DD], in place. block=128, grid=GG
__global__ void k_ln(float* __restrict__ t, const float* __restrict__ g,
                     const float* __restrict__ b) {
    int gid = blockIdx.x;
    int tid = threadIdx.x;
    float* row = t + (size_t)gid * DD;
    float v[3];
    float s = 0.f;
    #pragma unroll
    for (int i = 0; i < 3; i++) {
        int d = tid + i * 128;
        v[i] = (d < DD) ? row[d] : 0.f;
        s += v[i];
    }
    __shared__ float red[4];
    __shared__ float red2[4];
    for (int o = 16; o; o >>= 1) s += __shfl_xor_sync(~0u, s, o);
    if ((tid & 31) == 0) red[tid >> 5] = s;
    __syncthreads();
    s = red[0] + red[1] + red[2] + red[3];
    float mu = s / DD;
    float q = 0.f;
    #pragma unroll
    for (int i = 0; i < 3; i++) {
        int d = tid + i * 128;
        float dv = (d < DD) ? (v[i] - mu) : 0.f;
        q += dv * dv;
    }
    for (int o = 16; o; o >>= 1) q += __shfl_xor_sync(~0u, q, o);
    if ((tid & 31) == 0) red2[tid >> 5] = q;
    __syncthreads();
    q = red2[0] + red2[1] + red2[2] + red2[3];
    float rs = rsqrtf(q / DD + EPS);
    #pragma unroll
    for (int i = 0; i < 3; i++) {
        int d = tid + i * 128;
        if (d < DD) {
            float x = (v[i] - mu) * rs * g[d] + b[d];
            row[d] = fmaxf(x, 0.f);
        }
    }
}

// ---------------- TF32 tensor-core GEMM, cp.async double-buffered ----------------
// C[n,m] = epilogue( A[n,k] @ B[k,m] + bias[m] )
// mode 0: ReLU(x+bias); 1: BN+ReLU, also atomic-add into pool[batch]; 2: BN; 3: bias only
// B must be pre-rounded to tf32.

__device__ __forceinline__ void mma_tf32(float* c, const uint32_t* a, const uint32_t* b) {
    asm volatile(
        "mma.sync.aligned.m16n8k8.row.col.f32.tf32.tf32.f32 "
        "{%0,%1,%2,%3}, {%4,%5,%6,%7}, {%8,%9}, {%0,%1,%2,%3};\n"
        : "+f"(c[0]), "+f"(c[1]), "+f"(c[2]), "+f"(c[3])
        : "r"(a[0]), "r"(a[1]), "r"(a[2]), "r"(a[3]), "r"(b[0]), "r"(b[1]));
}

#define BM 128
#define BN 128
#define BK 32
#define AST 36    // As row stride
#define BST 136   // Bs row stride
#define SMEM_GEMM (2 * (BM * AST + BK * BST) * 4)

extern __shared__ float smem_dyn[];

__global__ __launch_bounds__(256) void k_gemm_tf32(const float* __restrict__ A,
                                                   const float* __restrict__ B,
                                                   float* __restrict__ C,
                                                   int Nrows, int K, int M,
                                                   const float* __restrict__ bias,
                                                   const float* __restrict__ bng,
                                                   const float* __restrict__ bnb,
                                                   const float* __restrict__ bnm,
                                                   const float* __restrict__ bnv,
                                                   float* __restrict__ pool,
                                                   const int* __restrict__ batch,
                                                   int mode) {
    float* As = smem_dyn;                      // [2][BM*AST]
    float* Bs = smem_dyn + 2 * BM * AST;       // [2][BK*BST]

    int tid = threadIdx.x;
    int warp = tid >> 5, lane = tid & 31;
    int warp_m = warp & 3;     // 4 warps over M, 32 rows each
    int warp_n = warp >> 2;    // 2 warps over N, 64 cols each
    int row0 = blockIdx.y * BM;
    int col0 = blockIdx.x * BN;
    int lq = lane >> 2, lr = lane & 3;

    float acc[2][8][4] = {};

    int ra = tid >> 3;            // A row 0..31 (+32p)
    int kq = (tid & 7) * 4;       // A k offset
    int kb = tid >> 5;            // B k row 0..7 (+8p)
    int nq = (tid & 31) * 4;      // B n offset
    int nT = (K + BK - 1) / BK;

    {
        #pragma unroll
        for (int p = 0; p < 4; p++) {
            int rr = ra + p * 32;
            int gr = row0 + rr, gk = kq;
            bool ok = (gr < Nrows && gk < K);
            unsigned d = (unsigned)__cvta_generic_to_shared(&As[rr * AST + kq]);
            const float* s = ok ? (A + (size_t)gr * K + gk) : A;
            int sz = ok ? 16 : 0;
            asm volatile("cp.async.ca.shared.global [%0], [%1], 16, %2;\n" :: "r"(d), "l"(s), "r"(sz));
        }
        #pragma unroll
        for (int p = 0; p < 4; p++) {
            int kr = kb + p * 8;
            int gk = kr, gc = col0 + nq;
            bool ok = (gk < K && gc < M);
            unsigned d = (unsigned)__cvta_generic_to_shared(&Bs[kr * BST + nq]);
            const float* s = ok ? (B + (size_t)gk * M + gc) : B;
            int sz = ok ? 16 : 0;
            asm volatile("cp.async.ca.shared.global [%0], [%1], 16, %2;\n" :: "r"(d), "l"(s), "r"(sz));
        }
        asm volatile("cp.async.commit_group;\n");
    }

    for (int t = 0; t < nT; t++) {
        asm volatile("cp.async.wait_group 0;\n");
        __syncthreads();
        if (t + 1 < nT) {
            int k0 = (t + 1) * BK;
            int buf = (t + 1) & 1;
            float* Asn = As + buf * BM * AST;
            float* Bsn = Bs + buf * BK * BST;
            #pragma unroll
            for (int p = 0; p < 4; p++) {
                int rr = ra + p * 32;
                int gr = row0 + rr, gk = k0 + kq;
                bool ok = (gr < Nrows && gk < K);
                unsigned d = (unsigned)__cvta_generic_to_shared(&Asn[rr * AST + kq]);
                const float* s = ok ? (A + (size_t)gr * K + gk) : A;
                int sz = ok ? 16 : 0;
                asm volatile("cp.async.ca.shared.global [%0], [%1], 16, %2;\n" :: "r"(d), "l"(s), "r"(sz));
            }
            #pragma unroll
            for (int p = 0; p < 4; p++) {
                int kr = kb + p * 8;
                int gk = k0 + kr, gc = col0 + nq;
                bool ok = (gk < K && gc < M);
                unsigned d = (unsigned)__cvta_generic_to_shared(&Bsn[kr * BST + nq]);
                const float* s = ok ? (B + (size_t)gk * M + gc) : B;
                int sz = ok ? 16 : 0;
                asm volatile("cp.async.ca.shared.global [%0], [%1], 16, %2;\n" :: "r"(d), "l"(s), "r"(sz));
            }
            asm volatile("cp.async.commit_group;\n");
        }

        const float* Asb = As + (t & 1) * BM * AST;
        const float* Bsb = Bs + (t & 1) * BK * BST;
        #pragma unroll
        for (int ks = 0; ks < 4; ks++) {
            int k8 = ks * 8;
            uint32_t af[2][4], bf[8][2];
            int ar = warp_m * 32 + lq;
            int ac = k8 + lr;
            #pragma unroll
            for (int mt = 0; mt < 2; mt++) {
                const float* base = Asb + (ar + mt * 16) * AST + ac;
                af[mt][0] = tf32u(base[0]);
                af[mt][1] = tf32u(base[8 * AST]);
                af[mt][2] = tf32u(base[4]);
                af[mt][3] = tf32u(base[8 * AST + 4]);
            }
            int bc = warp_n * 64 + lq;
            #pragma unroll
            for (int nt = 0; nt < 8; nt++) {
                const float* base = Bsb + (k8 + lr) * BST + bc + nt * 8;
                bf[nt][0] = __float_as_uint(base[0]);
                bf[nt][1] = __float_as_uint(base[4 * BST]);
            }
            #pragma unroll
            for (int mt = 0; mt < 2; mt++)
                #pragma unroll
                for (int nt = 0; nt < 8; nt++)
                    mma_tf32(acc[mt][nt], af[mt], bf[nt]);
        }
        __syncthreads();
    }

    // --- epilogue ---
    #pragma unroll
    for (int mt = 0; mt < 2; mt++) {
        #pragma unroll
        for (int i = 0; i < 4; i++) {
            int row = row0 + warp_m * 32 + mt * 16 + lq + (i >= 2 ? 8 : 0);
            if (row >= Nrows) continue;
            int bg = (mode == 1) ? batch[row] : 0;
            #pragma unroll
            for (int nt = 0; nt < 8; nt++) {
                int col = col0 + warp_n * 64 + nt * 8 + lr * 2 + (i & 1);
                if (col >= M) continue;
                float v = acc[mt][nt][i] + bias[col];
                if (mode == 0) {
                    v = fmaxf(v, 0.f);
                } else if (mode != 3) {
                    float sc = bng[col] * rsqrtf(bnv[col] + EPS);
                    v = (v - bnm[col]) * sc + bnb[col];
                    if (mode == 1) v = fmaxf(v, 0.f);
                }
                C[(size_t)row * M + col] = v;
                if (mode == 1) atomicAdd(&pool[(size_t)bg * DD + col], v);
            }
        }
    }
}

// ---------------- launch ----------------
extern "C" void kernel_launch(void* const* d_in, const int* in_sizes, int n_in,
                              void* d_out, int out_size) {
    const int*   x_atom  = (const int*)d_in[0];
    const int*   x_chir  = (const int*)d_in[1];
    const int*   src     = (const int*)d_in[2];
    const int*   dst     = (const int*)d_in[3];
    const int*   etype   = (const int*)d_in[4];
    const int*   edir    = (const int*)d_in[5];
    const int*   batch   = (const int*)d_in[6];
    const float* x_emb1  = (const float*)d_in[7];
    const float* x_emb2  = (const float*)d_in[8];
    const float* edge_e1 = (const float*)d_in[9];
    const float* edge_e2 = (const float*)d_in[10];
    const float* mlp_w1  = (const float*)d_in[11];
    const float* mlp_b1  = (const float*)d_in[12];
    const float* mlp_w2  = (const float*)d_in[13];
    const float* mlp_b2  = (const float*)d_in[14];
    const float* bng     = (const float*)d_in[15];
    const float* bnb     = (const float*)d_in[16];
    const float* bnm     = (const float*)d_in[17];
    const float* bnv     = (const float*)d_in[18];
    const float* vn_emb  = (const float*)d_in[19];
    const float* vn_w1   = (const float*)d_in[20];
    const float* vn_b1   = (const float*)d_in[21];
    const float* vn_lng  = (const float*)d_in[22];
    const float* vn_lnb  = (const float*)d_in[23];
    const float* vn_w2   = (const float*)d_in[24];
    const float* vn_b2   = (const float*)d_in[25];
    float* out = (float*)d_out;

    float *p_h, *p_aggr, *p_hid, *p_pool, *p_vn, *p_vnin, *p_vnt, *p_cnt;
    float *p_w1r, *p_w2r, *p_vw1r, *p_vw2r;
    int *p_tc, *p_dc;
    cudaGetSymbolAddress((void**)&p_h, g_h);
    cudaGetSymbolAddress((void**)&p_aggr, g_aggr);
    cudaGetSymbolAddress((void**)&p_hid, g_hid);
    cudaGetSymbolAddress((void**)&p_pool, g_pool);
    cudaGetSymbolAddress((void**)&p_vn, g_vn);
    cudaGetSymbolAddress((void**)&p_vnin, g_vnin);
    cudaGetSymbolAddress((void**)&p_vnt, g_vnt);
    cudaGetSymbolAddress((void**)&p_cnt, g_cnt);
    cudaGetSymbolAddress((void**)&p_w1r, g_w1r);
    cudaGetSymbolAddress((void**)&p_w2r, g_w2r);
    cudaGetSymbolAddress((void**)&p_vw1r, g_vw1r);
    cudaGetSymbolAddress((void**)&p_vw2r, g_vw2r);
    cudaGetSymbolAddress((void**)&p_tc, g_tc);
    cudaGetSymbolAddress((void**)&p_dc, g_dc);

    cudaFuncSetAttribute(k_gemm_tf32, cudaFuncAttributeMaxDynamicSharedMemorySize, SMEM_GEMM);

    const long ND = (long)NN * DD;
    const long GD = (long)GG * DD;
    const int TPB = 256;
    dim3 bElem((unsigned)((ND + TPB - 1) / TPB));
    dim3 bGD((unsigned)((GD + TPB - 1) / TPB));

    // pre-round weights to tf32 (B operands)
    {
        long n1 = (long)LL * DD * D2;
        long n2 = (long)LL * D2 * DD;
        long n3 = (long)(LL - 1) * DD * DD;
        k_round<<<(unsigned)((n1 + TPB - 1) / TPB), TPB>>>(mlp_w1, p_w1r, n1);
        k_round<<<(unsigned)((n2 + TPB - 1) / TPB), TPB>>>(mlp_w2, p_w2r, n2);
        k_round<<<(unsigned)((n3 + TPB - 1) / TPB), TPB>>>(vn_w1, p_vw1r, n3);
        k_round<<<(unsigned)((n3 + TPB - 1) / TPB), TPB>>>(vn_w2, p_vw2r, n3);
    }

    // counts + edge histograms (topology fixed across layers)
    k_zero<<<(GG + TPB - 1) / TPB, TPB>>>(p_cnt, GG);
    k_count<<<(NN + TPB - 1) / TPB, TPB>>>(batch, p_cnt, NN);
    k_zeroi<<<(unsigned)(((long)NN * 6 + TPB - 1) / TPB), TPB>>>(p_tc, (long)NN * 6);
    k_zeroi<<<(unsigned)(((long)NN * 3 + TPB - 1) / TPB), TPB>>>(p_dc, (long)NN * 3);
    k_edgehist<<<(EE + TPB - 1) / TPB, TPB>>>(dst, etype, edir, p_tc, p_dc, EE);

    // h0 and vn0
    k_init_h<<<bElem, TPB>>>(x_atom, x_chir, x_emb1, x_emb2, vn_emb, p_h, ND);
    k_init_vn<<<bGD, TPB>>>(vn_emb, p_vn, GD);

    for (int l = 0; l < LL; l++) {
        const float* e1l = edge_e1 + (size_t)l * 6 * DD;
        const float* e2l = edge_e2 + (size_t)l * 3 * DD;

        k_aggr_init<<<(NN + 7) / 8, 256>>>(p_h, e1l, e2l, p_tc, p_dc, p_aggr, NN);
        k_scatter<<<(EE + 3) / 4, 128>>>(p_h, src, dst, p_aggr, EE);

        if (l < LL - 1) k_zero<<<bGD, TPB>>>(p_pool, GD);  // pool target for fused epilogue

        // hidden = ReLU(aggr @ W1 + b1)   [N, 600]
        {
            dim3 grid((D2 + BN - 1) / BN, (NN + BM - 1) / BM);
            k_gemm_tf32<<<grid, 256, SMEM_GEMM>>>(p_aggr, p_w1r + (size_t)l * DD * D2, p_hid,
                                       NN, DD, D2, mlp_b1 + (size_t)l * D2,
                                       nullptr, nullptr, nullptr, nullptr, nullptr, nullptr, 0);
        }
        // z = BN(hidden @ W2 + b2)  (+ReLU + fused pool unless last layer)
        {
            float* zdst = (l == LL - 1) ? out : p_h;
            int mode = (l == LL - 1) ? 2 : 1;
            dim3 grid((DD + BN - 1) / BN, (NN + BM - 1) / BM);
            k_gemm_tf32<<<grid, 256, SMEM_GEMM>>>(p_hid, p_w2r + (size_t)l * D2 * DD, zdst,
                                       NN, D2, DD, mlp_b2 + (size_t)l * DD,
                                       bng + (size_t)l * DD, bnb + (size_t)l * DD,
                                       bnm + (size_t)l * DD, bnv + (size_t)l * DD,
                                       p_pool, batch, mode);
        }

        if (l < LL - 1) {
            k_vnprep<<<bGD, TPB>>>(p_pool, p_cnt, p_vn, p_vnin, GD);
            {
                dim3 grid((DD + BN - 1) / BN, (GG + BM - 1) / BM);
                k_gemm_tf32<<<grid, 256, SMEM_GEMM>>>(p_vnin, p_vw1r + (size_t)l * DD * DD, p_vnt,
                                           GG, DD, DD, vn_b1 + (size_t)l * DD,
                                           nullptr, nullptr, nullptr, nullptr, nullptr, nullptr, 3);
            }
            k_ln<<<GG, 128>>>(p_vnt, vn_lng + (size_t)l * DD, vn_lnb + (size_t)l * DD);
            {
                dim3 grid((DD + BN - 1) / BN, (GG + BM - 1) / BM);
                k_gemm_tf32<<<grid, 256, SMEM_GEMM>>>(p_vnt, p_vw2r + (size_t)l * DD * DD, p_vn,
                                           GG, DD, DD, vn_b2 + (size_t)l * DD,
                                           nullptr, nullptr, nullptr, nullptr, nullptr, nullptr, 3);
            }
            k_addvn<<<bElem, TPB>>>(p_h, p_vn, batch, ND);
        }
    }
}